// round 12
// baseline (speedup 1.0000x reference)
#include <cuda_runtime.h>
#include <cuda_bf16.h>
#include <math.h>
#include <stdint.h>

// Shapes
#define Bsz 16
#define CH 64
#define H1 14
#define W1 254
#define HWp (H1*W1)            // 3556
#define CHWp (CH*HWp)          // 227584
#define Ncap 28448
#define Ecls 8
#define ODv 16

// ---------------- scratch ----------------
__device__ float g_h1[Bsz*CHWp];
__device__ float g_y2[Bsz*CHWp];
__device__ float g_h3[Bsz*CHWp];
__device__ float g_u [Bsz*Ncap*8];
__device__ float g_s [3*2048];
__device__ float g_vsum[2048];
__device__ __nv_bfloat16 g_w2h[64*2304];
__device__ __nv_bfloat16 g_w2l[64*2304];

__global__ void zero_k() {
    int t = blockIdx.x*256 + threadIdx.x;
    if (t < 3*2048) g_s[t] = 0.f;
    if (t < 2048)   g_vsum[t] = 0.f;
}

// ---------------- prep: split w2 into bf16 hi/lo ----------------
__global__ void splitw2_k(const float* __restrict__ w2) {
    int i = blockIdx.x*256 + threadIdx.x;
    if (i < 64*2304) {
        float v = w2[i];
        __nv_bfloat16 h = __float2bfloat16(v);
        g_w2h[i] = h;
        g_w2l[i] = __float2bfloat16(v - __bfloat162float(h));
    }
}

// ---------------- conv1: 1->64ch 6x6 stride2, relu ----------------
__global__ void conv1_k(const float* __restrict__ x,
                        const float* __restrict__ w1,
                        const float* __restrict__ b1) {
    __shared__ float xs[6*512];
    __shared__ float ws[2304];
    __shared__ float bs[64];
    int h = blockIdx.x, b = blockIdx.y, t = threadIdx.x;
    const float* xrow = x + b*(32*512) + (2*h)*512;
    for (int j = t; j < 3072; j += 256) xs[j] = xrow[j];
    for (int j = t; j < 2304; j += 256) ws[j] = w1[j];
    if (t < 64) bs[t] = b1[t];
    __syncthreads();
    if (t >= W1) return;
    float win[36];
#pragma unroll
    for (int r = 0; r < 6; r++)
#pragma unroll
        for (int k = 0; k < 6; k++) win[r*6+k] = xs[r*512 + 2*t + k];
    float* outp = g_h1 + (size_t)(b*CH*H1 + h)*W1 + t;
    for (int f = 0; f < 64; f++) {
        float a = bs[f];
        const float* wp = ws + f*36;
#pragma unroll
        for (int k = 0; k < 36; k++) a = fmaf(win[k], wp[k], a);
        outp[(size_t)f*HWp] = fmaxf(a, 0.f);
    }
}

// ===== conv2: mma.sync bf16 3-term, ldmatrix frags, 2 CTA/SM ======
// Grid (2 wtiles, 14 h, 16 b). M=128 w-pos, N=64 couts.
// 32 K-chunks of 2 ci (72 taps, padded to 80). A stored k-major [80][136],
// B [64][88] double-buffered hi/lo via cp.async. Pads pre-zeroed.
#define LDP 136
#define LDB2 88
#define A_WORDS (80*LDP)                 // 10880 bf16 per tile
#define B_EL (64*LDB2)                   // 5632 bf16 per (buf,hl)
#define B_BYTES (B_EL*2)                 // 11264
#define RAWF 1632                        // 2ci x 6kh x 136 floats
#define C2_SMEM (RAWF*4 + 2*A_WORDS*2 + 4*B_EL*2)   // 95104

static __device__ __forceinline__ void mma16816(float* c,
    uint32_t a0, uint32_t a1, uint32_t a2, uint32_t a3,
    uint32_t b0, uint32_t b1) {
    asm volatile(
        "mma.sync.aligned.m16n8k16.row.col.f32.bf16.bf16.f32 "
        "{%0,%1,%2,%3}, {%4,%5,%6,%7}, {%8,%9}, {%0,%1,%2,%3};"
        : "+f"(c[0]), "+f"(c[1]), "+f"(c[2]), "+f"(c[3])
        : "r"(a0), "r"(a1), "r"(a2), "r"(a3), "r"(b0), "r"(b1));
}
static __device__ __forceinline__ void ldsm4(uint32_t& r0, uint32_t& r1,
    uint32_t& r2, uint32_t& r3, unsigned a) {
    asm volatile("ldmatrix.sync.aligned.m8n8.x4.shared.b16 {%0,%1,%2,%3}, [%4];"
        : "=r"(r0), "=r"(r1), "=r"(r2), "=r"(r3) : "r"(a));
}
static __device__ __forceinline__ void ldsm4t(uint32_t& r0, uint32_t& r1,
    uint32_t& r2, uint32_t& r3, unsigned a) {
    asm volatile("ldmatrix.sync.aligned.m8n8.x4.trans.shared.b16 {%0,%1,%2,%3}, [%4];"
        : "=r"(r0), "=r"(r1), "=r"(r2), "=r"(r3) : "r"(a));
}
__device__ __forceinline__ void cpa16g(unsigned d, const void* s) {
    asm volatile("cp.async.cg.shared.global [%0], [%1], 16;" :: "r"(d), "l"(s));
}

__global__ void __launch_bounds__(256, 2)
conv2_mma(const float* __restrict__ b2) {
    extern __shared__ char cs2[];
    float* raw = (float*)cs2;                         // [2][6][136] f32
    __nv_bfloat16* Ah = (__nv_bfloat16*)(cs2 + RAWF*4);
    __nv_bfloat16* Al = Ah + A_WORDS;
    __nv_bfloat16* Bb = Al + A_WORDS;                 // [buf2][hl2][64][LDB2]

    const int wt = blockIdx.x, h = blockIdx.y, b = blockIdx.z;
    const int t = threadIdx.x, lane = t & 31, wid = t >> 5;
    const int mbase = wid * 16;
    const int w0 = wt * 128;

    const unsigned sAh = (unsigned)__cvta_generic_to_shared(Ah);
    const unsigned sAl = (unsigned)__cvta_generic_to_shared(Al);
    const unsigned sB  = (unsigned)__cvta_generic_to_shared(Bb);

    float acc[8][4];
#pragma unroll
    for (int nt = 0; nt < 8; nt++)
#pragma unroll
        for (int q = 0; q < 4; q++) acc[nt][q] = 0.f;

    // zero static pads: A k-rows 72..79 (both tiles), B k 72..79 (all 4 bufs)
    for (int j = t; j < 1088; j += 256) {             // 2 x 544 words
        int arr = j >= 544, r = j - arr*544;
        ((uint32_t*)(arr ? Al : Ah))[72*(LDP/2) + r] = 0u;
    }
    for (int j = t; j < 1024; j += 256) {             // 4 bufs x 64 n x 4 words
        int bufhl = j >> 8, r = j & 255;
        int n = r >> 2, w = r & 3;
        ((uint32_t*)(Bb + bufhl*B_EL))[n*(LDB2/2) + 36 + w] = 0u;
    }

    auto stageB = [&](int chunk, int buf) {
#pragma unroll
        for (int i = 0; i < 5; i++) {
            int idx = t + i*256;                      // 1152 = 2hl x 64co x 9
            if (idx < 1152) {
                int hl = idx >= 576;
                int r = idx - hl*576;
                int co = r / 9, j = r - co*9;
                const __nv_bfloat16* src = (hl ? g_w2l : g_w2h)
                    + co*2304 + chunk*72 + j*8;
                cpa16g(sB + (unsigned)(buf*2 + hl)*B_BYTES
                          + (unsigned)(co*LDB2 + j*8)*2, src);
            }
        }
        asm volatile("cp.async.commit_group;");
    };

    stageB(0, 0);

    // lane-invariant ldmatrix offsets
    const int lrow = (lane & 7) + ((lane >> 4) & 1)*8;
    const int lcolsel = ((lane >> 3) & 1)*8;
    const unsigned aoffA = (unsigned)(lrow*LDP + mbase + lcolsel)*2;
    const unsigned aoffB = (unsigned)(lrow*LDB2 + lcolsel)*2;

    for (int chunk = 0; chunk < 32; chunk++) {
        const int ci0 = chunk * 2;
        const int buf = chunk & 1;
        __syncthreads();                              // prior mma done
        // ---- stage raw rows (fp32, guarded) ----
        for (int j = t; j < RAWF; j += 256) {
            int ci = j / 816; int r2 = j - ci*816;
            int rr = r2 / 136; int wc = r2 - rr*136;
            int hin = h + rr - 2, winn = w0 - 2 + wc;
            float v = 0.f;
            if (hin >= 0 && hin < H1 && (unsigned)winn < (unsigned)W1)
                v = g_h1[((size_t)(b*CH + ci0 + ci)*H1 + hin)*W1 + winn];
            raw[j] = v;
        }
        __syncthreads();
        // ---- expand raw -> k-major A hi/lo (coalesced STS.32) ----
#pragma unroll
        for (int i = 0; i < 3; i++) {
            int idx = t + i*256;                      // 768 = 12(ci,kh) x 64 p2
            int p2 = idx & 63, g = idx >> 6;
            int ci = g / 6, kh = g - ci*6;
            int p = p2 * 2;
            const float* rp = raw + ci*816 + kh*136 + p;
            float f[7];
#pragma unroll
            for (int j = 0; j < 7; j++) f[j] = rp[j];
            __nv_bfloat16 hb[7]; float hf[7]; __nv_bfloat16 lb[7];
#pragma unroll
            for (int j = 0; j < 7; j++) {
                hb[j] = __float2bfloat16(f[j]);
                hf[j] = __bfloat162float(hb[j]);
                lb[j] = __float2bfloat16(f[j] - hf[j]);
            }
            int k0 = ci*36 + kh*6;
#pragma unroll
            for (int j = 0; j < 6; j++) {
                __nv_bfloat162 h2; h2.x = hb[j]; h2.y = hb[j+1];
                __nv_bfloat162 l2; l2.x = lb[j]; l2.y = lb[j+1];
                *(__nv_bfloat162*)(Ah + (k0+j)*LDP + p) = h2;
                *(__nv_bfloat162*)(Al + (k0+j)*LDP + p) = l2;
            }
        }
        // ---- prefetch next B, wait current ----
        if (chunk < 31) {
            stageB(chunk + 1, buf ^ 1);
            asm volatile("cp.async.wait_group 1;");
        } else {
            asm volatile("cp.async.wait_group 0;");
        }
        __syncthreads();

        // ---- MMA: 5 k16 frags ----
        const unsigned bhBase = sB + (unsigned)(buf*2)*B_BYTES + aoffB;
#pragma unroll
        for (int kf = 0; kf < 5; kf++) {
            unsigned ka = aoffA + (unsigned)kf*16*LDP*2;
            uint32_t ah0,ah1,ah2,ah3, al0,al1,al2,al3;
            ldsm4t(ah0, ah1, ah2, ah3, sAh + ka);
            ldsm4t(al0, al1, al2, al3, sAl + ka);
            unsigned kb = (unsigned)kf*32;
#pragma unroll
            for (int bq = 0; bq < 4; bq++) {
                unsigned boff = bhBase + (unsigned)bq*16*LDB2*2 + kb;
                uint32_t bh0,bh1,bh2,bh3, bl0,bl1,bl2,bl3;
                ldsm4(bh0, bh1, bh2, bh3, boff);
                ldsm4(bl0, bl1, bl2, bl3, boff + B_BYTES);
                mma16816(acc[2*bq],   ah0,ah1,ah2,ah3, bh0,bh1);
                mma16816(acc[2*bq],   ah0,ah1,ah2,ah3, bl0,bl1);
                mma16816(acc[2*bq],   al0,al1,al2,al3, bh0,bh1);
                mma16816(acc[2*bq+1], ah0,ah1,ah2,ah3, bh2,bh3);
                mma16816(acc[2*bq+1], ah0,ah1,ah2,ah3, bl2,bl3);
                mma16816(acc[2*bq+1], al0,al1,al2,al3, bh2,bh3);
            }
        }
    }

    // ---- epilogue: bias + relu + store ----
    {
        int p0 = mbase + (lane >> 2);
        int p1 = p0 + 8;
        int wA = w0 + p0, wBp = w0 + p1;
        bool v0 = wA < W1, v1 = wBp < W1;
        float* orow = g_y2 + ((size_t)(b*CH)*H1 + h)*W1;
#pragma unroll
        for (int nt = 0; nt < 8; nt++) {
            int co = nt*8 + 2*(lane & 3);
            float bb0 = __ldg(b2 + co), bb1 = __ldg(b2 + co + 1);
            if (v0) {
                orow[(size_t)co*HWp + wA]     = fmaxf(acc[nt][0] + bb0, 0.f);
                orow[(size_t)(co+1)*HWp + wA] = fmaxf(acc[nt][1] + bb1, 0.f);
            }
            if (v1) {
                orow[(size_t)co*HWp + wBp]     = fmaxf(acc[nt][2] + bb0, 0.f);
                orow[(size_t)(co+1)*HWp + wBp] = fmaxf(acc[nt][3] + bb1, 0.f);
            }
        }
    }
}

// ---------------- conv3: 1x1, 128->64 ch, 32-cout groups ----------
__global__ void __launch_bounds__(256)
conv3_k(const float* __restrict__ w3, const float* __restrict__ b3) {
    __shared__ float ws[32*128];
    int t = threadIdx.x;
    int co0 = blockIdx.y * 32;
    for (int j = t; j < 4096; j += 256)
        ws[j] = w3[(co0 + (j >> 7))*128 + (j & 127)];
    __syncthreads();
    int p0 = blockIdx.x*1024 + t*4;
    if (p0 >= Bsz*HWp) return;
    int b = p0 / HWp, hw = p0 - b*HWp;
    const float* ih = g_h1 + (size_t)b*CHWp + hw;
    const float* iy = g_y2 + (size_t)b*CHWp + hw;
    float4 acc[32];
#pragma unroll
    for (int k = 0; k < 32; k++) {
        float bb = b3[co0+k];
        acc[k] = make_float4(bb, bb, bb, bb);
    }
#pragma unroll 2
    for (int ci = 0; ci < 64; ci++) {
        float4 xh = *(const float4*)(ih + (size_t)ci*HWp);
        float4 xy = *(const float4*)(iy + (size_t)ci*HWp);
#pragma unroll
        for (int k = 0; k < 32; k++) {
            float wh = ws[k*128 + ci], wy = ws[k*128 + 64 + ci];
            acc[k].x = fmaf(xh.x, wh, acc[k].x);
            acc[k].y = fmaf(xh.y, wh, acc[k].y);
            acc[k].z = fmaf(xh.z, wh, acc[k].z);
            acc[k].w = fmaf(xh.w, wh, acc[k].w);
            acc[k].x = fmaf(xy.x, wy, acc[k].x);
            acc[k].y = fmaf(xy.y, wy, acc[k].y);
            acc[k].z = fmaf(xy.z, wy, acc[k].z);
            acc[k].w = fmaf(xy.w, wy, acc[k].w);
        }
    }
#pragma unroll
    for (int k = 0; k < 32; k++)
        *(float4*)(g_h3 + (size_t)b*CHWp + (size_t)(co0+k)*HWp + hw) = acc[k];
}

// ---------------- primary capsules ----------
__global__ void pc_k(const float* __restrict__ pw, const float* __restrict__ pb) {
    int n = blockIdx.x*256 + threadIdx.x;
    int b = blockIdx.y;
    if (n >= Ncap) return;
    const float4* uin = (const float4*)(g_h3 + (size_t)b*CHWp + (size_t)n*8);
    float4 q0 = uin[0], q1 = uin[1];
    float ui[8] = {q0.x,q0.y,q0.z,q0.w, q1.x,q1.y,q1.z,q1.w};
    const float4* pbv = (const float4*)(pb + (size_t)n*8);
    float4 r0 = pbv[0], r1 = pbv[1];
    float a[8] = {r0.x,r0.y,r0.z,r0.w, r1.x,r1.y,r1.z,r1.w};
    const float4* pwv = (const float4*)(pw + (size_t)n*64);
#pragma unroll
    for (int i = 0; i < 8; i++) {
        float4 wA = pwv[2*i], wB = pwv[2*i+1];
        a[0] = fmaf(ui[i], wA.x, a[0]); a[1] = fmaf(ui[i], wA.y, a[1]);
        a[2] = fmaf(ui[i], wA.z, a[2]); a[3] = fmaf(ui[i], wA.w, a[3]);
        a[4] = fmaf(ui[i], wB.x, a[4]); a[5] = fmaf(ui[i], wB.y, a[5]);
        a[6] = fmaf(ui[i], wB.z, a[6]); a[7] = fmaf(ui[i], wB.w, a[7]);
    }
    float4* uo = (float4*)(g_u + ((size_t)b*Ncap + n)*8);
    uo[0] = make_float4(a[0],a[1],a[2],a[3]);
    uo[1] = make_float4(a[4],a[5],a[6],a[7]);
}

// ---------------- routing pass: cp.async pipelined, conflict-free -----
#define RGROUP 6
#define RCHUNK 66
#define ECROW 132
#define ECN (Ecls*ECROW)
#define R_SMEM_BYTES ((2*RGROUP*ECN + 2*RGROUP*128) * 4)

__device__ __forceinline__ void cpa16(unsigned d, const void* s) {
    asm volatile("cp.async.cg.shared.global [%0], [%1], 16;" :: "r"(d), "l"(s));
}

__global__ void __launch_bounds__(128)
route_k(const float* __restrict__ ec, int pass) {
    extern __shared__ float rs[];
    float* ecs = rs;
    float* us  = rs + 2*RGROUP*ECN;
    int t = threadIdx.x;
    int b = t >> 3, e = t & 7;
    float* sout = g_s + pass*2048;

    float vs[16];
    const float4* vp = (const float4*)(g_vsum + t*16);
#pragma unroll
    for (int q = 0; q < 4; q++) {
        float4 v = vp[q];
        vs[q*4+0] = v.x; vs[q*4+1] = v.y; vs[q*4+2] = v.z; vs[q*4+3] = v.w;
    }
    float accs[16];
#pragma unroll
    for (int o = 0; o < 16; o++) accs[o] = 0.f;

    int n0 = blockIdx.x * RCHUNK;
    int nEnd = n0 + RCHUNK; if (nEnd > Ncap) nEnd = Ncap;
    int gTot = (nEnd - n0 + RGROUP - 1) / RGROUP;

    auto stage = [&](int g, int buf) {
        int nb = n0 + g*RGROUP;
        unsigned ecd = (unsigned)__cvta_generic_to_shared(ecs + buf*RGROUP*ECN);
        unsigned usd = (unsigned)__cvta_generic_to_shared(us  + buf*RGROUP*128);
#pragma unroll
        for (int j = 0; j < 12; j++) {
            int idx = t + j*128;
            int nl = idx >> 8, c = idx & 255;
            int n = nb + nl;
            if (n < nEnd)
                cpa16(ecd + (unsigned)(nl*ECN + (c>>5)*ECROW + (c&31)*4)*4u,
                      ec + (size_t)n*1024 + c*4);
        }
#pragma unroll
        for (int j = 0; j < 2; j++) {
            int idx = t + j*128;
            if (idx < RGROUP*32) {
                int nl = idx >> 5, lane = idx & 31;
                int n = nb + nl;
                int bb = lane >> 1, half = lane & 1;
                if (n < nEnd)
                    cpa16(usd + (unsigned)(nl*128 + bb*8 + half*4)*4u,
                          g_u + ((size_t)bb*Ncap + n)*8 + half*4);
            }
        }
        asm volatile("cp.async.commit_group;");
    };

    stage(0, 0);
    for (int g = 0; g < gTot; g++) {
        if (g + 1 < gTot) {
            stage(g+1, (g+1)&1);
            asm volatile("cp.async.wait_group 1;");
        } else {
            asm volatile("cp.async.wait_group 0;");
        }
        __syncthreads();
        int cnt = nEnd - (n0 + g*RGROUP);
        if (cnt > RGROUP) cnt = RGROUP;
        const float* eb = ecs + (g&1)*RGROUP*ECN;
        const float* ub = us  + (g&1)*RGROUP*128;
        for (int nl = 0; nl < cnt; nl++) {
            const float* un = ub + nl*128 + b*8;
            float4 u0 = *(const float4*)un;
            float4 u1 = *(const float4*)(un + 4);
            float ubv[8] = {u0.x,u0.y,u0.z,u0.w, u1.x,u1.y,u1.z,u1.w};
            const float4* ep = (const float4*)(eb + nl*ECN + e*ECROW);
            float uh[16];
            float bl = 0.f;
#pragma unroll
            for (int o = 0; o < 16; o++) {
                float4 wA = ep[2*o], wB = ep[2*o+1];
                float s = wA.x*ubv[0] + wA.y*ubv[1] + wA.z*ubv[2] + wA.w*ubv[3]
                        + wB.x*ubv[4] + wB.y*ubv[5] + wB.z*ubv[6] + wB.w*ubv[7];
                uh[o] = s;
                bl = fmaf(s, vs[o], bl);
            }
            float m = bl;
            m = fmaxf(m, __shfl_xor_sync(0xffffffffu, m, 1));
            m = fmaxf(m, __shfl_xor_sync(0xffffffffu, m, 2));
            m = fmaxf(m, __shfl_xor_sync(0xffffffffu, m, 4));
            float ex = __expf(bl - m);
            float den = ex;
            den += __shfl_xor_sync(0xffffffffu, den, 1);
            den += __shfl_xor_sync(0xffffffffu, den, 2);
            den += __shfl_xor_sync(0xffffffffu, den, 4);
            float c = ex / den;
#pragma unroll
            for (int o = 0; o < 16; o++) accs[o] = fmaf(c, uh[o], accs[o]);
        }
        __syncthreads();
    }
#pragma unroll
    for (int o = 0; o < 16; o++) atomicAdd(sout + t*16 + o, accs[o]);
}

// ---------------- squash + accumulate vsum ----------------
__global__ void squash_k(int pass) {
    int t = threadIdx.x;
    const float* sp = g_s + pass*2048 + t*16;
    float sv[16]; float nn = 0.f;
#pragma unroll
    for (int o = 0; o < 16; o++) { sv[o] = sp[o]; nn = fmaf(sv[o], sv[o], nn); }
    float nrm = sqrtf(nn);
    float sc = nn / (1.f + nn) / (nrm + 1e-8f);
#pragma unroll
    for (int o = 0; o < 16; o++) g_vsum[t*16 + o] += sc * sv[o];
}

__global__ void final_k(float* __restrict__ out) {
    int t = threadIdx.x;
    const float* sp = g_s + 2*2048 + t*16;
    float nn = 0.f;
#pragma unroll
    for (int o = 0; o < 16; o++) { float v = sp[o]; nn = fmaf(v, v, nn); }
    float nrm = sqrtf(nn);
    float sc = nn / (1.f + nn) / (nrm + 1e-8f);
    out[t] = sc * nrm;
}

// ---------------- launch ----------------
extern "C" void kernel_launch(void* const* d_in, const int* in_sizes, int n_in,
                              void* d_out, int out_size) {
    const float* x  = (const float*)d_in[0];
    const float* w1 = (const float*)d_in[1];
    const float* b1 = (const float*)d_in[2];
    const float* w2 = (const float*)d_in[3];
    const float* b2 = (const float*)d_in[4];
    const float* w3 = (const float*)d_in[5];
    const float* b3 = (const float*)d_in[6];
    const float* pw = (const float*)d_in[7];
    const float* pb = (const float*)d_in[8];
    const float* ec = (const float*)d_in[9];
    float* out = (float*)d_out;

    cudaFuncSetAttribute(conv2_mma, cudaFuncAttributeMaxDynamicSharedMemorySize,
                         C2_SMEM);
    cudaFuncSetAttribute(route_k, cudaFuncAttributeMaxDynamicSharedMemorySize,
                         R_SMEM_BYTES);

    zero_k<<<24, 256>>>();
    splitw2_k<<<(64*2304 + 255)/256, 256>>>(w2);
    conv1_k<<<dim3(H1, Bsz), 256>>>(x, w1, b1);
    conv2_mma<<<dim3(2, H1, Bsz), 256, C2_SMEM>>>(b2);
    conv3_k<<<dim3(56, 2), 256>>>(w3, b3);
    pc_k<<<dim3((Ncap + 255)/256, Bsz), 256>>>(pw, pb);

    int rblocks = (Ncap + RCHUNK - 1) / RCHUNK;
    route_k<<<rblocks, 128, R_SMEM_BYTES>>>(ec, 0);
    squash_k<<<1, 128>>>(0);
    route_k<<<rblocks, 128, R_SMEM_BYTES>>>(ec, 1);
    squash_k<<<1, 128>>>(1);
    route_k<<<rblocks, 128, R_SMEM_BYTES>>>(ec, 2);
    final_k<<<1, 128>>>(out);
}

// round 13
// speedup vs baseline: 1.2455x; 1.2455x over previous
#include <cuda_runtime.h>
#include <cuda_bf16.h>
#include <math.h>
#include <stdint.h>

// Shapes
#define Bsz 16
#define CH 64
#define H1 14
#define W1 254
#define HWp (H1*W1)            // 3556
#define CHWp (CH*HWp)          // 227584
#define Ncap 28448
#define Ecls 8
#define ODv 16

// padded NHWC planes for conv2 A operand: rows -2..16 (19), cols -2..261 (264)
#define PRows 19
#define PCols 264
#define PLANE_E ((size_t)Bsz*PRows*PCols*64)   // 5,136,384 bf16

// ---------------- scratch ----------------
__device__ float g_h1[Bsz*CHWp];
__device__ float g_y2[Bsz*CHWp];
__device__ float g_h3[Bsz*CHWp];
__device__ float g_u [Bsz*Ncap*8];
__device__ float g_s [3*2048];
__device__ float g_vsum[2048];
__device__ __nv_bfloat16 g_h1h[PLANE_E];
__device__ __nv_bfloat16 g_h1l[PLANE_E];
__device__ __nv_bfloat16 g_w2t[36*2*4096];   // [tap][hl][co][ci]

__global__ void zero_k() {
    int t = blockIdx.x*256 + threadIdx.x;
    if (t < 3*2048) g_s[t] = 0.f;
    if (t < 2048)   g_vsum[t] = 0.f;
}
__global__ void zerop_k() {
    size_t i = (size_t)blockIdx.x*256 + threadIdx.x;
    size_t n = PLANE_E/8;
    uint4 z = make_uint4(0,0,0,0);
    for (size_t j = i; j < n; j += (size_t)gridDim.x*256) {
        ((uint4*)g_h1h)[j] = z;
        ((uint4*)g_h1l)[j] = z;
    }
}

// ---------------- prep: transpose+split w2 -> [tap][hl][co][ci] bf16 ----
__global__ void splitw2_k(const float* __restrict__ w2) {
    int i = blockIdx.x*256 + threadIdx.x;
    if (i < 64*2304) {
        int co = i / 2304, r = i - co*2304;
        int ci = r / 36, tap = r - ci*36;
        float v = w2[i];
        __nv_bfloat16 h = __float2bfloat16(v);
        __nv_bfloat16 l = __float2bfloat16(v - __bfloat162float(h));
        g_w2t[(tap*2+0)*4096 + co*64 + ci] = h;
        g_w2t[(tap*2+1)*4096 + co*64 + ci] = l;
    }
}

// ---------------- conv1: 1->64ch 6x6 s2, relu; fp32 + NHWC bf16 hi/lo ----
__global__ void conv1_k(const float* __restrict__ x,
                        const float* __restrict__ w1,
                        const float* __restrict__ b1) {
    __shared__ float xs[6*512];
    __shared__ float ws[2304];
    __shared__ float bs[64];
    int h = blockIdx.x, b = blockIdx.y, t = threadIdx.x;
    const float* xrow = x + b*(32*512) + (2*h)*512;
    for (int j = t; j < 3072; j += 256) xs[j] = xrow[j];
    for (int j = t; j < 2304; j += 256) ws[j] = w1[j];
    if (t < 64) bs[t] = b1[t];
    __syncthreads();
    if (t >= W1) return;
    float win[36];
#pragma unroll
    for (int r = 0; r < 6; r++)
#pragma unroll
        for (int k = 0; k < 6; k++) win[r*6+k] = xs[r*512 + 2*t + k];
    float* outp = g_h1 + (size_t)(b*CH*H1 + h)*W1 + t;
    uint32_t* ph = (uint32_t*)(g_h1h + (((size_t)b*PRows + h+2)*PCols + t+2)*64);
    uint32_t* pl = (uint32_t*)(g_h1l + (((size_t)b*PRows + h+2)*PCols + t+2)*64);
    for (int f = 0; f < 64; f += 2) {
        float a0 = bs[f], a1 = bs[f+1];
        const float* wp0 = ws + f*36;
        const float* wp1 = wp0 + 36;
#pragma unroll
        for (int k = 0; k < 36; k++) {
            a0 = fmaf(win[k], wp0[k], a0);
            a1 = fmaf(win[k], wp1[k], a1);
        }
        a0 = fmaxf(a0, 0.f); a1 = fmaxf(a1, 0.f);
        outp[(size_t)f*HWp]     = a0;
        outp[(size_t)(f+1)*HWp] = a1;
        __nv_bfloat162 hv = __floats2bfloat162_rn(a0, a1);
        __nv_bfloat162 lv = __floats2bfloat162_rn(
            a0 - __bfloat162float(hv.x), a1 - __bfloat162float(hv.y));
        ph[f>>1] = *(uint32_t*)&hv;
        pl[f>>1] = *(uint32_t*)&lv;
    }
}

// ===== conv2: tap-decomposed GEMM, pure-cp.async staging, ldmatrix ======
// Grid (2 wtiles, 14 h, 16 b). M=128 pos (8 warps x m16), N=64 co.
// 36 taps (kh,kw), K=64 ci per tap, 3-term bf16 hi/lo.
#define AROWS 134
#define A_PB (AROWS*128)            // bytes per (buf,hl) A tile: 17152
#define B_PB (64*128)               // bytes per (buf,hl) B tile: 8192
#define C2S_A (4*A_PB)              // 68608
#define C2S_B (4*B_PB)              // 32768
#define C2_SMEM (C2S_A + C2S_B)     // 101376

static __device__ __forceinline__ void mma16816(float* c,
    uint32_t a0, uint32_t a1, uint32_t a2, uint32_t a3,
    uint32_t b0, uint32_t b1) {
    asm volatile(
        "mma.sync.aligned.m16n8k16.row.col.f32.bf16.bf16.f32 "
        "{%0,%1,%2,%3}, {%4,%5,%6,%7}, {%8,%9}, {%0,%1,%2,%3};"
        : "+f"(c[0]), "+f"(c[1]), "+f"(c[2]), "+f"(c[3])
        : "r"(a0), "r"(a1), "r"(a2), "r"(a3), "r"(b0), "r"(b1));
}
static __device__ __forceinline__ void ldsm4(uint32_t& r0, uint32_t& r1,
    uint32_t& r2, uint32_t& r3, unsigned a) {
    asm volatile("ldmatrix.sync.aligned.m8n8.x4.shared.b16 {%0,%1,%2,%3}, [%4];"
        : "=r"(r0), "=r"(r1), "=r"(r2), "=r"(r3) : "r"(a));
}
__device__ __forceinline__ void cpa16g(unsigned d, const void* s) {
    asm volatile("cp.async.cg.shared.global [%0], [%1], 16;" :: "r"(d), "l"(s));
}

__global__ void __launch_bounds__(256, 2)
conv2_mma(const float* __restrict__ b2) {
    extern __shared__ char cs2[];
    unsigned sA, sB;
    { unsigned u; asm("{ .reg .u64 tp; cvta.to.shared.u64 tp, %1; cvt.u32.u64 %0, tp; }"
                      : "=r"(u) : "l"(cs2));
      sA = u; sB = u + C2S_A; }

    const int wt = blockIdx.x, h = blockIdx.y, b = blockIdx.z;
    const int t = threadIdx.x, lane = t & 31, wid = t >> 5;
    const int mbase = wid * 16;
    const int w0 = wt * 128;

    float acc[8][4];
#pragma unroll
    for (int nt = 0; nt < 8; nt++)
#pragma unroll
        for (int q = 0; q < 4; q++) acc[nt][q] = 0.f;

    auto stageA = [&](int kh, int buf) {
        const char* ph = (const char*)(g_h1h + (((size_t)b*PRows + h+kh)*PCols + w0)*64);
        const char* pl = (const char*)(g_h1l + (((size_t)b*PRows + h+kh)*PCols + w0)*64);
#pragma unroll
        for (int i = 0; i < 9; i++) {
            int idx = t + i*256;                 // 2144 = 2hl x 134pp x 8c
            if (idx < 2144) {
                int hl = idx >= 1072;
                int r = idx - hl*1072;
                int pp = r >> 3, c = r & 7;
                cpa16g(sA + (unsigned)((buf*2+hl)*A_PB + pp*128 + ((c^(pp&7))*16)),
                       (hl ? pl : ph) + pp*128 + c*16);
            }
        }
        asm volatile("cp.async.commit_group;");
    };
    auto stageB = [&](int tap, int buf) {
#pragma unroll
        for (int i = 0; i < 4; i++) {
            int idx = t + i*256;                 // 1024 = 2hl x 64co x 8c
            int hl = idx >> 9;
            int r = idx & 511;
            int co = r >> 3, c = r & 7;
            cpa16g(sB + (unsigned)((buf*2+hl)*B_PB + co*128 + ((c^(co&7))*16)),
                   (const char*)(g_w2t + (size_t)(tap*2+hl)*4096 + co*64) + c*16);
        }
        asm volatile("cp.async.commit_group;");
    };

    stageA(0, 0);
    stageB(0, 0);
    stageB(1, 1);
    asm volatile("cp.async.wait_group 1;");      // A0,B0 done; B1 pending
    __syncthreads();

    // lane-constant frag index pieces
    const int arsel = (lane & 7) + ((lane >> 3) & 1)*8;   // m within 16
    const int acsel = (lane >> 4) & 1;                    // k8 select (A)
    const int brsel = (lane & 7) + ((lane >> 4) & 1)*8;   // n within 16
    const int bcsel = (lane >> 3) & 1;                    // k8 select (B)

    for (int kh = 0; kh < 6; kh++) {
        const unsigned aHi = sA + (unsigned)(kh & 1)*2*A_PB;
#pragma unroll 1
        for (int kw = 0; kw < 6; kw++) {
            const int tap = kh*6 + kw;
            if (tap > 0) __syncthreads();        // mma(tap-1) done block-wide
            if (tap >= 1 && tap + 1 <= 35) stageB(tap + 1, (tap + 1) & 1);
            if (kw == 4 && kh < 5) stageA(kh + 1, (kh + 1) & 1);
            asm volatile("cp.async.wait_group 1;");
            __syncthreads();                     // visibility

            const unsigned bHi = sB + (unsigned)(tap & 1)*2*B_PB;
            const int arow = mbase + kw + arsel;
            const unsigned aBase = aHi + (unsigned)(arow*128);
            const int axr = (arow & 7);
#pragma unroll
            for (int kf = 0; kf < 4; kf++) {
                int ac = kf*2 + acsel;
                unsigned aaddr = aBase + (unsigned)(((ac ^ axr))*16);
                uint32_t ah0,ah1,ah2,ah3, al0,al1,al2,al3;
                ldsm4(ah0, ah1, ah2, ah3, aaddr);
                ldsm4(al0, al1, al2, al3, aaddr + A_PB);
                int bc = kf*2 + bcsel;
#pragma unroll
                for (int bq = 0; bq < 4; bq++) {
                    int bro = bq*16 + brsel;
                    unsigned baddr = bHi + (unsigned)(bro*128 + ((bc ^ (bro&7))*16));
                    uint32_t bh0,bh1,bh2,bh3, bl0,bl1,bl2,bl3;
                    ldsm4(bh0, bh1, bh2, bh3, baddr);
                    ldsm4(bl0, bl1, bl2, bl3, baddr + B_PB);
                    mma16816(acc[2*bq],   ah0,ah1,ah2,ah3, bh0,bh1);
                    mma16816(acc[2*bq],   ah0,ah1,ah2,ah3, bl0,bl1);
                    mma16816(acc[2*bq],   al0,al1,al2,al3, bh0,bh1);
                    mma16816(acc[2*bq+1], ah0,ah1,ah2,ah3, bh2,bh3);
                    mma16816(acc[2*bq+1], ah0,ah1,ah2,ah3, bl2,bl3);
                    mma16816(acc[2*bq+1], al0,al1,al2,al3, bh2,bh3);
                }
            }
        }
    }

    // ---- epilogue: bias + relu + store ----
    {
        int p0 = mbase + (lane >> 2);
        int p1 = p0 + 8;
        int wA = w0 + p0, wBp = w0 + p1;
        bool v0 = wA < W1, v1 = wBp < W1;
        float* orow = g_y2 + ((size_t)(b*CH)*H1 + h)*W1;
#pragma unroll
        for (int nt = 0; nt < 8; nt++) {
            int co = nt*8 + 2*(lane & 3);
            float bb0 = __ldg(b2 + co), bb1 = __ldg(b2 + co + 1);
            if (v0) {
                orow[(size_t)co*HWp + wA]     = fmaxf(acc[nt][0] + bb0, 0.f);
                orow[(size_t)(co+1)*HWp + wA] = fmaxf(acc[nt][1] + bb1, 0.f);
            }
            if (v1) {
                orow[(size_t)co*HWp + wBp]     = fmaxf(acc[nt][2] + bb0, 0.f);
                orow[(size_t)(co+1)*HWp + wBp] = fmaxf(acc[nt][3] + bb1, 0.f);
            }
        }
    }
}

// ---------------- conv3: 1x1, 128->64 ch, 32-cout groups ----------
__global__ void __launch_bounds__(256)
conv3_k(const float* __restrict__ w3, const float* __restrict__ b3) {
    __shared__ float ws[32*128];
    int t = threadIdx.x;
    int co0 = blockIdx.y * 32;
    for (int j = t; j < 4096; j += 256)
        ws[j] = w3[(co0 + (j >> 7))*128 + (j & 127)];
    __syncthreads();
    int p0 = blockIdx.x*1024 + t*4;
    if (p0 >= Bsz*HWp) return;
    int b = p0 / HWp, hw = p0 - b*HWp;
    const float* ih = g_h1 + (size_t)b*CHWp + hw;
    const float* iy = g_y2 + (size_t)b*CHWp + hw;
    float4 acc[32];
#pragma unroll
    for (int k = 0; k < 32; k++) {
        float bb = b3[co0+k];
        acc[k] = make_float4(bb, bb, bb, bb);
    }
#pragma unroll 2
    for (int ci = 0; ci < 64; ci++) {
        float4 xh = *(const float4*)(ih + (size_t)ci*HWp);
        float4 xy = *(const float4*)(iy + (size_t)ci*HWp);
#pragma unroll
        for (int k = 0; k < 32; k++) {
            float wh = ws[k*128 + ci], wy = ws[k*128 + 64 + ci];
            acc[k].x = fmaf(xh.x, wh, acc[k].x);
            acc[k].y = fmaf(xh.y, wh, acc[k].y);
            acc[k].z = fmaf(xh.z, wh, acc[k].z);
            acc[k].w = fmaf(xh.w, wh, acc[k].w);
            acc[k].x = fmaf(xy.x, wy, acc[k].x);
            acc[k].y = fmaf(xy.y, wy, acc[k].y);
            acc[k].z = fmaf(xy.z, wy, acc[k].z);
            acc[k].w = fmaf(xy.w, wy, acc[k].w);
        }
    }
#pragma unroll
    for (int k = 0; k < 32; k++)
        *(float4*)(g_h3 + (size_t)b*CHWp + (size_t)(co0+k)*HWp + hw) = acc[k];
}

// ---------------- primary capsules ----------
__global__ void pc_k(const float* __restrict__ pw, const float* __restrict__ pb) {
    int n = blockIdx.x*256 + threadIdx.x;
    int b = blockIdx.y;
    if (n >= Ncap) return;
    const float4* uin = (const float4*)(g_h3 + (size_t)b*CHWp + (size_t)n*8);
    float4 q0 = uin[0], q1 = uin[1];
    float ui[8] = {q0.x,q0.y,q0.z,q0.w, q1.x,q1.y,q1.z,q1.w};
    const float4* pbv = (const float4*)(pb + (size_t)n*8);
    float4 r0 = pbv[0], r1 = pbv[1];
    float a[8] = {r0.x,r0.y,r0.z,r0.w, r1.x,r1.y,r1.z,r1.w};
    const float4* pwv = (const float4*)(pw + (size_t)n*64);
#pragma unroll
    for (int i = 0; i < 8; i++) {
        float4 wA = pwv[2*i], wB = pwv[2*i+1];
        a[0] = fmaf(ui[i], wA.x, a[0]); a[1] = fmaf(ui[i], wA.y, a[1]);
        a[2] = fmaf(ui[i], wA.z, a[2]); a[3] = fmaf(ui[i], wA.w, a[3]);
        a[4] = fmaf(ui[i], wB.x, a[4]); a[5] = fmaf(ui[i], wB.y, a[5]);
        a[6] = fmaf(ui[i], wB.z, a[6]); a[7] = fmaf(ui[i], wB.w, a[7]);
    }
    float4* uo = (float4*)(g_u + ((size_t)b*Ncap + n)*8);
    uo[0] = make_float4(a[0],a[1],a[2],a[3]);
    uo[1] = make_float4(a[4],a[5],a[6],a[7]);
}

// ---------------- routing pass: cp.async pipelined, conflict-free -----
#define RGROUP 6
#define RCHUNK 66
#define ECROW 132
#define ECN (Ecls*ECROW)
#define R_SMEM_BYTES ((2*RGROUP*ECN + 2*RGROUP*128) * 4)

__device__ __forceinline__ void cpa16(unsigned d, const void* s) {
    asm volatile("cp.async.cg.shared.global [%0], [%1], 16;" :: "r"(d), "l"(s));
}

__global__ void __launch_bounds__(128)
route_k(const float* __restrict__ ec, int pass) {
    extern __shared__ float rs[];
    float* ecs = rs;
    float* us  = rs + 2*RGROUP*ECN;
    int t = threadIdx.x;
    int b = t >> 3, e = t & 7;
    float* sout = g_s + pass*2048;

    float vs[16];
    const float4* vp = (const float4*)(g_vsum + t*16);
#pragma unroll
    for (int q = 0; q < 4; q++) {
        float4 v = vp[q];
        vs[q*4+0] = v.x; vs[q*4+1] = v.y; vs[q*4+2] = v.z; vs[q*4+3] = v.w;
    }
    float accs[16];
#pragma unroll
    for (int o = 0; o < 16; o++) accs[o] = 0.f;

    int n0 = blockIdx.x * RCHUNK;
    int nEnd = n0 + RCHUNK; if (nEnd > Ncap) nEnd = Ncap;
    int gTot = (nEnd - n0 + RGROUP - 1) / RGROUP;

    auto stage = [&](int g, int buf) {
        int nb = n0 + g*RGROUP;
        unsigned ecd = (unsigned)__cvta_generic_to_shared(ecs + buf*RGROUP*ECN);
        unsigned usd = (unsigned)__cvta_generic_to_shared(us  + buf*RGROUP*128);
#pragma unroll
        for (int j = 0; j < 12; j++) {
            int idx = t + j*128;
            int nl = idx >> 8, c = idx & 255;
            int n = nb + nl;
            if (n < nEnd)
                cpa16(ecd + (unsigned)(nl*ECN + (c>>5)*ECROW + (c&31)*4)*4u,
                      ec + (size_t)n*1024 + c*4);
        }
#pragma unroll
        for (int j = 0; j < 2; j++) {
            int idx = t + j*128;
            if (idx < RGROUP*32) {
                int nl = idx >> 5, lane = idx & 31;
                int n = nb + nl;
                int bb = lane >> 1, half = lane & 1;
                if (n < nEnd)
                    cpa16(usd + (unsigned)(nl*128 + bb*8 + half*4)*4u,
                          g_u + ((size_t)bb*Ncap + n)*8 + half*4);
            }
        }
        asm volatile("cp.async.commit_group;");
    };

    stage(0, 0);
    for (int g = 0; g < gTot; g++) {
        if (g + 1 < gTot) {
            stage(g+1, (g+1)&1);
            asm volatile("cp.async.wait_group 1;");
        } else {
            asm volatile("cp.async.wait_group 0;");
        }
        __syncthreads();
        int cnt = nEnd - (n0 + g*RGROUP);
        if (cnt > RGROUP) cnt = RGROUP;
        const float* eb = ecs + (g&1)*RGROUP*ECN;
        const float* ub = us  + (g&1)*RGROUP*128;
        for (int nl = 0; nl < cnt; nl++) {
            const float* un = ub + nl*128 + b*8;
            float4 u0 = *(const float4*)un;
            float4 u1 = *(const float4*)(un + 4);
            float ubv[8] = {u0.x,u0.y,u0.z,u0.w, u1.x,u1.y,u1.z,u1.w};
            const float4* ep = (const float4*)(eb + nl*ECN + e*ECROW);
            float uh[16];
            float bl = 0.f;
#pragma unroll
            for (int o = 0; o < 16; o++) {
                float4 wA = ep[2*o], wB = ep[2*o+1];
                float s = wA.x*ubv[0] + wA.y*ubv[1] + wA.z*ubv[2] + wA.w*ubv[3]
                        + wB.x*ubv[4] + wB.y*ubv[5] + wB.z*ubv[6] + wB.w*ubv[7];
                uh[o] = s;
                bl = fmaf(s, vs[o], bl);
            }
            float m = bl;
            m = fmaxf(m, __shfl_xor_sync(0xffffffffu, m, 1));
            m = fmaxf(m, __shfl_xor_sync(0xffffffffu, m, 2));
            m = fmaxf(m, __shfl_xor_sync(0xffffffffu, m, 4));
            float ex = __expf(bl - m);
            float den = ex;
            den += __shfl_xor_sync(0xffffffffu, den, 1);
            den += __shfl_xor_sync(0xffffffffu, den, 2);
            den += __shfl_xor_sync(0xffffffffu, den, 4);
            float c = ex / den;
#pragma unroll
            for (int o = 0; o < 16; o++) accs[o] = fmaf(c, uh[o], accs[o]);
        }
        __syncthreads();
    }
#pragma unroll
    for (int o = 0; o < 16; o++) atomicAdd(sout + t*16 + o, accs[o]);
}

// ---------------- squash + accumulate vsum ----------------
__global__ void squash_k(int pass) {
    int t = threadIdx.x;
    const float* sp = g_s + pass*2048 + t*16;
    float sv[16]; float nn = 0.f;
#pragma unroll
    for (int o = 0; o < 16; o++) { sv[o] = sp[o]; nn = fmaf(sv[o], sv[o], nn); }
    float nrm = sqrtf(nn);
    float sc = nn / (1.f + nn) / (nrm + 1e-8f);
#pragma unroll
    for (int o = 0; o < 16; o++) g_vsum[t*16 + o] += sc * sv[o];
}

__global__ void final_k(float* __restrict__ out) {
    int t = threadIdx.x;
    const float* sp = g_s + 2*2048 + t*16;
    float nn = 0.f;
#pragma unroll
    for (int o = 0; o < 16; o++) { float v = sp[o]; nn = fmaf(v, v, nn); }
    float nrm = sqrtf(nn);
    float sc = nn / (1.f + nn) / (nrm + 1e-8f);
    out[t] = sc * nrm;
}

// ---------------- launch ----------------
extern "C" void kernel_launch(void* const* d_in, const int* in_sizes, int n_in,
                              void* d_out, int out_size) {
    const float* x  = (const float*)d_in[0];
    const float* w1 = (const float*)d_in[1];
    const float* b1 = (const float*)d_in[2];
    const float* w2 = (const float*)d_in[3];
    const float* b2 = (const float*)d_in[4];
    const float* w3 = (const float*)d_in[5];
    const float* b3 = (const float*)d_in[6];
    const float* pw = (const float*)d_in[7];
    const float* pb = (const float*)d_in[8];
    const float* ec = (const float*)d_in[9];
    float* out = (float*)d_out;

    cudaFuncSetAttribute(conv2_mma, cudaFuncAttributeMaxDynamicSharedMemorySize,
                         C2_SMEM);
    cudaFuncSetAttribute(route_k, cudaFuncAttributeMaxDynamicSharedMemorySize,
                         R_SMEM_BYTES);

    zero_k<<<24, 256>>>();
    zerop_k<<<2048, 256>>>();
    splitw2_k<<<(64*2304 + 255)/256, 256>>>(w2);
    conv1_k<<<dim3(H1, Bsz), 256>>>(x, w1, b1);
    conv2_mma<<<dim3(2, H1, Bsz), 256, C2_SMEM>>>(b2);
    conv3_k<<<dim3(56, 2), 256>>>(w3, b3);
    pc_k<<<dim3((Ncap + 255)/256, Bsz), 256>>>(pw, pb);

    int rblocks = (Ncap + RCHUNK - 1) / RCHUNK;
    route_k<<<rblocks, 128, R_SMEM_BYTES>>>(ec, 0);
    squash_k<<<1, 128>>>(0);
    route_k<<<rblocks, 128, R_SMEM_BYTES>>>(ec, 1);
    squash_k<<<1, 128>>>(1);
    route_k<<<rblocks, 128, R_SMEM_BYTES>>>(ec, 2);
    final_k<<<1, 128>>>(out);
}